// round 16
// baseline (speedup 1.0000x reference)
#include <cuda_runtime.h>
#include <cstdint>

// Problem: B=8, C=256, H=W=64, K=3, pad=1, stride=1
// out_flat[f] = keyflat[f] * qv[f/9], f in [0, 9*4096) per (b,c) slice
// CTA = (slice bc, quarter q): l in [q*1024, q*1024+1024), all 9 kk.
// 128 threads; thread owns 8 consecutive l per kk -> one STG.256 (v8.f32) per kk.
// f = f0 + 4096*kk, f0 = q*1024 + 8*tid, 4096 = 9*455+1:
//   lp0(kk) = a0 + 455*kk + cr,  cr = [r0+kk >= 9],  rem = r0+kk - 9*cr
//   element j (0..7) uses qv[lp0+1] iff rem + j >= 9  (single crossing: 8 < 9)
//   window base(kk) = b0 + 455*kk (b0 = q*1024/9); idx = (kk<<7) + (a0-b0) + cr
#define HW   64
#define KP   68                 // key tile pitch (1 left halo + 64 + 3 right pad)
#define KR   18                 // image rows q*16-1 .. q*16+16
#define QW   128                // qv window stride (power of 2; 116 used)
#define QVT  (9 * QW)           // 1152
#define LSZ  4096

__device__ __forceinline__ float qpatch(const float* __restrict__ qb, int lp) {
    // qv[lp] = zero-padded query at fq = 9*lp + 4
    float v = 0.0f;
    if ((unsigned)lp < (unsigned)LSZ) {
        const int fq  = 9 * lp + 4;
        const int kkq = fq >> 12;
        const int lq  = fq & 4095;
        const int row = (lq >> 6) + kkq / 3 - 1;
        const int col = (lq & 63) + kkq % 3 - 1;
        if (((unsigned)row < (unsigned)HW) & ((unsigned)col < (unsigned)HW))
            v = __ldg(qb + row * HW + col);
    }
    return v;
}

__device__ __forceinline__ void stg256_cs(float* p, const float* o) {
    asm volatile(
        "st.global.cs.v8.f32 [%0], {%1,%2,%3,%4,%5,%6,%7,%8};"
        :: "l"(p), "f"(o[0]), "f"(o[1]), "f"(o[2]), "f"(o[3]),
           "f"(o[4]), "f"(o[5]), "f"(o[6]), "f"(o[7])
        : "memory");
}

__global__ void __launch_bounds__(128, 16)
appearance_kernel(const float* __restrict__ key,
                  const float* __restrict__ query,
                  float* __restrict__ out) {
    __shared__ alignas(32) float ktile[KR * KP];   // 4896 B
    __shared__ alignas(16) float qvs[QVT];         // 4608 B

    const int tid = threadIdx.x;                   // 0..127
    const int bid = blockIdx.x;        // 0..8191
    const int bc  = bid >> 2;          // slice 0..2047
    const int q   = bid & 3;           // quarter 0..3
    const int q1024 = q << 10;

    const float4* kb4 = (const float4*)(key + (size_t)bc * LSZ);
    const float*  qb  = query + (size_t)bc * LSZ;

    // ---- zero halo columns (cols 0, 65, 66, 67 of all 18 rows; 72 cells) ----
    if (tid < KR * 4) {
        const int lr = tid >> 2, hc = tid & 3;
        ktile[lr * KP + (hc == 0 ? 0 : 64 + hc)] = 0.0f;
    }

    // ---- key tile: local row lr = image row (q*16 - 1 + lr); 288 f4 tiles ----
    #pragma unroll
    for (int k = 0; k < 2; k++) {
        const int i = tid + k * 128;               // tiles 0..255
        const int lr = i >> 4, c4 = i & 15;
        const int ir = q * 16 - 1 + lr;
        float4 v = make_float4(0.f, 0.f, 0.f, 0.f);
        if ((unsigned)ir < (unsigned)HW) v = kb4[ir * 16 + c4];
        float* p = &ktile[lr * KP + 1 + c4 * 4];
        p[0] = v.x; p[1] = v.y; p[2] = v.z; p[3] = v.w;
    }
    if (tid < 32) {                                // tiles 256..287 (rows 16,17)
        const int i = tid + 256;
        const int lr = i >> 4, c4 = i & 15;
        const int ir = q * 16 - 1 + lr;
        float4 v = make_float4(0.f, 0.f, 0.f, 0.f);
        if ((unsigned)ir < (unsigned)HW) v = kb4[ir * 16 + c4];
        float* p = &ktile[lr * KP + 1 + c4 * 4];
        p[0] = v.x; p[1] = v.y; p[2] = v.z; p[3] = v.w;
    }

    // ---- qv windows: qvs[(kk<<7)+jj] = qv[b0 + 455*kk + jj]; pure-add fill ----
    const unsigned b0 = (unsigned)q1024 / 9u;      // uniform per CTA
    #pragma unroll
    for (int k = 0; k < 9; k++) {                  // 1152 = 9*128, unpredicated
        const int j = tid + k * 128;
        const int kk = j >> 7;
        const int jj = j & 127;
        qvs[j] = qpatch(qb, (int)b0 + 455 * kk + jj);
    }
    __syncthreads();

    // ---- per-thread division ONCE; loop is adds/compares only ----
    const int f0 = q1024 + (tid << 3);             // 8 floats per thread per kk
    const unsigned a0 = (unsigned)f0 / 9u;         // one mul-hi div
    const int r0 = f0 - (int)a0 * 9;               // 0..8
    const int d0 = (int)(a0 - b0);                 // 0..113

    float* outp = out + (size_t)bc * 36864 + q1024 + (tid << 3);
    const int lrow = tid >> 3;                     // 0..15
    const int col  = (tid & 7) << 3;               // 0..56, 32B aligned

    #pragma unroll
    for (int dr = 0; dr < 3; dr++) {
        // 10-word window serves dc=0..2 for 8 outputs: cols col..col+9
        const float* wp = &ktile[(lrow + dr) * KP + col];
        const float4 A = *(const float4*)wp;        // w0..w3
        const float4 B = *(const float4*)(wp + 4);  // w4..w7
        const float2 C = *(const float2*)(wp + 8);  // w8,w9
        float w[10] = {A.x, A.y, A.z, A.w, B.x, B.y, B.z, B.w, C.x, C.y};

        #pragma unroll
        for (int dc = 0; dc < 3; dc++) {
            const int kk  = 3 * dr + dc;
            const int rk  = r0 + kk;               // 0..16
            const int cr  = (rk >= 9) ? 1 : 0;
            const int rem = rk - (cr ? 9 : 0);     // 0..8
            const int idx = (kk << 7) + d0 + cr;
            const float q0 = qvs[idx];
            const float qn = qvs[idx + 1];

            float o[8];
            #pragma unroll
            for (int j = 0; j < 8; j++)
                o[j] = w[dc + j] * ((rem + j >= 9) ? qn : q0);

            stg256_cs(outp + kk * LSZ, o);         // one STG.256 per kk
        }
    }
}

extern "C" void kernel_launch(void* const* d_in, const int* in_sizes, int n_in,
                              void* d_out, int out_size) {
    const float* key   = (const float*)d_in[0];
    const float* query = (const float*)d_in[1];
    float* out = (float*)d_out;

    appearance_kernel<<<8192, 128>>>(key, query, out);
}

// round 17
// speedup vs baseline: 1.0218x; 1.0218x over previous
#include <cuda_runtime.h>
#include <cstdint>

// Problem: B=8, C=256, H=W=64, K=3, pad=1, stride=1
// out_flat[f] = keyflat[f] * qv[f/9], f in [0, 9*4096) per (b,c) slice
//   keyflat[f] = zero-padded key at (l>>6 + kk/3 - 1, (l&63) + kk%3 - 1)
//   qv[l']     = zero-padded query at fq = 9*l'+4 (same patch formula)
// CTA = (slice bc, quarter q): l in [q*1024, q*1024+1024), all 9 kk.
// f = f0 + 4096*kk, 4096 = 9*455+1:
//   lp0(kk) = a0 + 455*kk + cr,  cr = [r0+kk >= 9],  rem = r0+kk - 9*cr
//   window base(kk) = b0 + 455*kk exactly (b0 = q*1024/9)
//   idx into window kk: (kk<<7) + (a0-b0) + cr      (QW = 128, d0 <= 113)
//
// FINAL (R10 champion). Ablations measured on sm_103a, kernel us:
//   store: .cs 54.9 | .wb 55.0 | .wt 56.8 | v8.cs 56.3      -> STG.128 .cs
//   CTA: 256thr/quarter 54.9 | 512/half 56.8 | 128/quarter 56.3
//   split: l-quarter 54.9 | kk-group 62.0 | f-contig 59.7
//   smem: linear 54.9 | plane-split 72.4
//   Limit: 302MB write stream @ ~5.5TB/s effective pure-write DRAM throughput.
#define HW   64
#define KP   68                 // key tile pitch (1 left halo + 64 + 3 right pad)
#define KR   18                 // image rows q*16-1 .. q*16+16
#define QW   128                // qv window stride (power of 2; 116 used)
#define QVT  (9 * QW)           // 1152
#define LSZ  4096

__device__ __forceinline__ float qpatch(const float* __restrict__ qb, int lp) {
    // qv[lp] = zero-padded query at fq = 9*lp + 4
    float v = 0.0f;
    if ((unsigned)lp < (unsigned)LSZ) {
        const int fq  = 9 * lp + 4;
        const int kkq = fq >> 12;
        const int lq  = fq & 4095;
        const int row = (lq >> 6) + kkq / 3 - 1;
        const int col = (lq & 63) + kkq % 3 - 1;
        if (((unsigned)row < (unsigned)HW) & ((unsigned)col < (unsigned)HW))
            v = __ldg(qb + row * HW + col);
    }
    return v;
}

__global__ void __launch_bounds__(256, 8)
appearance_kernel(const float* __restrict__ key,
                  const float* __restrict__ query,
                  float* __restrict__ out) {
    __shared__ alignas(16) float ktile[KR * KP];   // 4896 B
    __shared__ alignas(16) float qvs[QVT];         // 4608 B

    const int tid = threadIdx.x;
    const int bid = blockIdx.x;        // 0..8191
    const int bc  = bid >> 2;          // slice 0..2047
    const int q   = bid & 3;           // quarter 0..3
    const int q1024 = q << 10;

    const float*  kb  = key   + (size_t)bc * LSZ;
    const float4* kb4 = (const float4*)kb;
    const float*  qb  = query + (size_t)bc * LSZ;

    // ---- zero halo columns (cols 0, 65, 66, 67 of all 18 rows) ----
    if (tid < KR * 4) {
        const int lr = tid >> 2, hc = tid & 3;
        ktile[lr * KP + (hc == 0 ? 0 : 64 + hc)] = 0.0f;
    }

    // ---- key tile: local row lr = image row (q*16 - 1 + lr) ----
    #pragma unroll
    for (int k = 0; k < 2; k++) {
        const int i = tid + k * 256;               // need 288 of 512
        if (i < KR * 16) {
            const int lr = i >> 4, c4 = i & 15;
            const int ir = q * 16 - 1 + lr;
            float4 v = make_float4(0.f, 0.f, 0.f, 0.f);
            if ((unsigned)ir < (unsigned)HW) v = kb4[ir * 16 + c4];
            float* p = &ktile[lr * KP + 1 + c4 * 4];
            p[0] = v.x; p[1] = v.y; p[2] = v.z; p[3] = v.w;
        }
    }

    // ---- qv windows: qvs[(kk<<7)+jj] = qv[b0 + 455*kk + jj]; pure-add fill ----
    const unsigned b0 = (unsigned)q1024 / 9u;      // uniform per CTA
    #pragma unroll
    for (int k = 0; k < 5; k++) {
        const int j = tid + k * 256;               // need 1152 of 1280
        if (j < QVT) {
            const int kk = j >> 7;                 // shift, no div
            const int jj = j & 127;
            const int lp = (int)b0 + 455 * kk + jj;
            qvs[j] = qpatch(qb, lp);               // bounds-checked (lp may be 4096)
        }
    }
    __syncthreads();

    // ---- per-thread division ONCE; loop is adds/compares only ----
    const int f0 = q1024 + (tid << 2);
    const unsigned a0 = (unsigned)f0 / 9u;         // one mul-hi div
    const int r0 = f0 - (int)a0 * 9;               // 0..8
    const int d0 = (int)(a0 - b0);                 // 0..113

    float4* out4 = (float4*)out + (size_t)bc * 9216 + q * 256 + tid;
    const int lrow = tid >> 4;                     // 0..15
    const int col  = (tid & 15) << 2;              // 0..60, 16B aligned

    #pragma unroll
    for (int dr = 0; dr < 3; dr++) {
        const float* wp = &ktile[(lrow + dr) * KP + col];
        const float4 a = *(const float4*)wp;       // w0..w3
        const float2 b = *(const float2*)(wp + 4); // w4,w5
        const float w0 = a.x, w1 = a.y, w2 = a.z, w3 = a.w, w4 = b.x, w5 = b.y;

        #pragma unroll
        for (int dc = 0; dc < 3; dc++) {
            const int kk  = 3 * dr + dc;
            const int rk  = r0 + kk;               // 0..16
            const int cr  = (rk >= 9) ? 1 : 0;
            const int rem = rk - (cr ? 9 : 0);     // 0..8
            const int idx = (kk << 7) + d0 + cr;
            const float q0 = qvs[idx];
            const float qn = qvs[idx + 1];

            float4 o;
            o.x = (dc == 0 ? w0 : dc == 1 ? w1 : w2) * q0;
            o.y = (dc == 0 ? w1 : dc == 1 ? w2 : w3) * (rem >= 8 ? qn : q0);
            o.z = (dc == 0 ? w2 : dc == 1 ? w3 : w4) * (rem >= 7 ? qn : q0);
            o.w = (dc == 0 ? w3 : dc == 1 ? w4 : w5) * (rem >= 6 ? qn : q0);
            __stcs(&out4[kk * 1024], o);           // streaming store
        }
    }
}

extern "C" void kernel_launch(void* const* d_in, const int* in_sizes, int n_in,
                              void* d_out, int out_size) {
    const float* key   = (const float*)d_in[0];
    const float* query = (const float*)d_in[1];
    float* out = (float*)d_out;

    appearance_kernel<<<8192, 256>>>(key, query, out);
}